// round 7
// baseline (speedup 1.0000x reference)
#include <cuda_runtime.h>

typedef unsigned long long ull;

// ---- packed f32x2 helpers (Blackwell sm_100+) ----
__device__ __forceinline__ ull pk2(float x, float y) {
    ull r; asm("mov.b64 %0, {%1, %2};" : "=l"(r) : "f"(x), "f"(y)); return r;
}
__device__ __forceinline__ ull dup2(float x) {
    ull r; asm("mov.b64 %0, {%1, %1};" : "=l"(r) : "f"(x)); return r;
}
__device__ __forceinline__ void fma2(ull& d, ull a, ull b) {
    asm("fma.rn.f32x2 %0, %1, %2, %0;" : "+l"(d) : "l"(a), "l"(b));
}
__device__ __forceinline__ float2 upk2(ull v) {
    float2 r; asm("mov.b64 {%0, %1}, %2;" : "=f"(r.x), "=f"(r.y) : "l"(v)); return r;
}

// Algebra:
//   layer-1 preact z1[j] = TAB[da*10+db][j] + p0 * d1[j]
//     TAB[idx][j] = Ea[da]·W1[j,0:8] + Eb[db]·W1[j,8:16] + b1[j] + W1[j,17]
//     d1[j]       = W1[j,16] - W1[j,17]
//   carry = softmax(c) = (p0, 1-p0) with p0 = sigmoid(c0 - c1)
//
// Parallelization: 2 threads per batch row (lane pair). Each thread owns
// 16 of the 32 h2 outputs (8 packed accumulators), computes the 12-wide
// head partials from its half, then the pair sums via shfl.xor(1).
// This halves register pressure -> zero local memory (hard requirement).

__global__ void mlp_seq_kernel(const int* __restrict__ A, const int* __restrict__ Bd,
                    const float* __restrict__ Ea, const float* __restrict__ Eb,
                    const float* __restrict__ W1, const float* __restrict__ b1,
                    const float* __restrict__ W2, const float* __restrict__ b2,
                    const float* __restrict__ Wd, const float* __restrict__ bd,
                    const float* __restrict__ Wc, const float* __restrict__ bc,
                    float* __restrict__ out, int Bn)
{
    __shared__ float sTABt[64][100];                  // sTABt[j][idx], idx = da*10+db
    __shared__ float sD1[64];
    __shared__ __align__(16) ull sW2p[64][2][8];      // [j][half][i4] = (W2[16h+2i4][j], W2[16h+2i4+1][j])
    __shared__ __align__(16) ull sB2ph[2][8];         // packed b2 per half
    __shared__ __align__(16) ull sWop[32][6];         // [i][k2] = (Wo[2k2][i], Wo[2k2+1][i]), Wo=[Wd;Wc]
    __shared__ ull sBop[6];

    const int tid = threadIdx.x;

    // ---------------- per-block precompute (amortized over 64x64 steps) ----------------
    for (int t = tid; t < 64; t += 128)
        sD1[t] = W1[t * 18 + 16] - W1[t * 18 + 17];

    for (int t = tid; t < 64 * 16; t += 128) {
        int j = t >> 4, half = (t >> 3) & 1, i4 = t & 7;
        int r0 = 16 * half + 2 * i4;
        sW2p[j][half][i4] = pk2(W2[r0 * 64 + j], W2[(r0 + 1) * 64 + j]);
    }
    if (tid < 16) {
        int half = tid >> 3, i4 = tid & 7;
        int r0 = 16 * half + 2 * i4;
        sB2ph[half][i4] = pk2(b2[r0], b2[r0 + 1]);
    }

    for (int t = tid; t < 32 * 6; t += 128) {
        int i = t / 6, k2 = t % 6;
        int k0 = 2 * k2, k1 = 2 * k2 + 1;
        float w0 = (k0 < 10) ? Wd[k0 * 32 + i] : Wc[(k0 - 10) * 32 + i];
        float w1 = (k1 < 10) ? Wd[k1 * 32 + i] : Wc[(k1 - 10) * 32 + i];
        sWop[i][k2] = pk2(w0, w1);
    }
    if (tid < 6) {
        int k0 = 2 * tid, k1 = k0 + 1;
        float v0 = (k0 < 10) ? bd[k0] : bc[k0 - 10];
        float v1 = (k1 < 10) ? bd[k1] : bc[k1 - 10];
        sBop[tid] = pk2(v0, v1);
    }

    for (int t = tid; t < 64 * 100; t += 128) {
        int j = t / 100, idx = t - j * 100;
        int da = idx / 10, db = idx - da * 10;
        const float* w = W1 + j * 18;
        float s = b1[j] + w[17];
#pragma unroll
        for (int k = 0; k < 8; k++) s = fmaf(Ea[da * 8 + k], w[k], s);
#pragma unroll
        for (int k = 0; k < 8; k++) s = fmaf(Eb[db * 8 + k], w[8 + k], s);
        sTABt[j][idx] = s;
    }
    __syncthreads();

    // ---------------- main recurrence: lane pair = 1 batch row ----------------
    int bi = (blockIdx.x * 128 + tid) >> 1;
    const int half = tid & 1;
    if (bi >= Bn) bi = Bn - 1;                 // duplicate tail work, same values written

    const long long rowoff = (long long)bi * 64;
    const int* ap  = A  + rowoff;
    const int* bpp = Bd + rowoff;
    float2* oD = (float2*)out + rowoff * 5;                       // digit logits [B,L,10]
    float2* oC = (float2*)(out + (long long)Bn * 640) + rowoff;   // carry logits [B,L,2]

    float p0 = 1.0f;                 // carry0 = (1, 0)
    int da = ap[0], db = bpp[0];

#pragma unroll 1
    for (int l = 0; l < 64; l++) {
        const int idx = da * 10 + db;
        const int nl = (l < 63) ? (l + 1) : 63;   // prefetch next digits
        da = ap[nl]; db = bpp[nl];

        // ---- fused layer-1 + half of the W2 GEMV ----
        ull acc0 = sB2ph[half][0], acc1 = sB2ph[half][1];
        ull acc2 = sB2ph[half][2], acc3 = sB2ph[half][3];
        ull acc4 = sB2ph[half][4], acc5 = sB2ph[half][5];
        ull acc6 = sB2ph[half][6], acc7 = sB2ph[half][7];

#pragma unroll 4
        for (int j = 0; j < 64; j++) {
            float t = sTABt[j][idx];
            float h = fmaxf(fmaf(p0, sD1[j], t), 0.0f);
            ull x = dup2(h);
            const ulonglong2* wr = (const ulonglong2*)&sW2p[j][half][0];
            ulonglong2 w0 = wr[0];
            fma2(acc0, w0.x, x); fma2(acc1, w0.y, x);
            ulonglong2 w1 = wr[1];
            fma2(acc2, w1.x, x); fma2(acc3, w1.y, x);
            ulonglong2 w2 = wr[2];
            fma2(acc4, w2.x, x); fma2(acc5, w2.y, x);
            ulonglong2 w3 = wr[3];
            fma2(acc6, w3.x, x); fma2(acc7, w3.y, x);
        }

        // ---- head partials over this half's 16 h2 values ----
        // bias only on half 0 (pair sum must count it once)
        ull o0, o1, o2, o3, o4, o5;
        if (half == 0) { o0 = sBop[0]; o1 = sBop[1]; o2 = sBop[2];
                         o3 = sBop[3]; o4 = sBop[4]; o5 = sBop[5]; }
        else           { o0 = o1 = o2 = o3 = o4 = o5 = 0ull; }

        const int ibase = 16 * half;
        ull accs[8] = {acc0, acc1, acc2, acc3, acc4, acc5, acc6, acc7};
#pragma unroll
        for (int i4 = 0; i4 < 8; i4++) {
            float2 hv = upk2(accs[i4]);
            float ha = fmaxf(hv.x, 0.0f);
            float hb = fmaxf(hv.y, 0.0f);
            ull xa = dup2(ha), xb = dup2(hb);
            const ulonglong2* wa = (const ulonglong2*)sWop[ibase + 2 * i4];
            const ulonglong2* wb = (const ulonglong2*)sWop[ibase + 2 * i4 + 1];
            ulonglong2 wa0 = wa[0], wa1 = wa[1], wa2 = wa[2];
            fma2(o0, wa0.x, xa); fma2(o1, wa0.y, xa);
            fma2(o2, wa1.x, xa); fma2(o3, wa1.y, xa);
            fma2(o4, wa2.x, xa); fma2(o5, wa2.y, xa);
            ulonglong2 wb0 = wb[0], wb1 = wb[1], wb2 = wb[2];
            fma2(o0, wb0.x, xb); fma2(o1, wb0.y, xb);
            fma2(o2, wb1.x, xb); fma2(o3, wb1.y, xb);
            fma2(o4, wb2.x, xb); fma2(o5, wb2.y, xb);
        }

        // ---- pair reduction: both lanes end with the full 12 outputs ----
        float2 r0 = upk2(o0), r1 = upk2(o1), r2 = upk2(o2);
        float2 r3 = upk2(o3), r4 = upk2(o4), cv = upk2(o5);
        r0.x += __shfl_xor_sync(0xFFFFFFFFu, r0.x, 1);
        r0.y += __shfl_xor_sync(0xFFFFFFFFu, r0.y, 1);
        r1.x += __shfl_xor_sync(0xFFFFFFFFu, r1.x, 1);
        r1.y += __shfl_xor_sync(0xFFFFFFFFu, r1.y, 1);
        r2.x += __shfl_xor_sync(0xFFFFFFFFu, r2.x, 1);
        r2.y += __shfl_xor_sync(0xFFFFFFFFu, r2.y, 1);
        r3.x += __shfl_xor_sync(0xFFFFFFFFu, r3.x, 1);
        r3.y += __shfl_xor_sync(0xFFFFFFFFu, r3.y, 1);
        r4.x += __shfl_xor_sync(0xFFFFFFFFu, r4.x, 1);
        r4.y += __shfl_xor_sync(0xFFFFFFFFu, r4.y, 1);
        cv.x += __shfl_xor_sync(0xFFFFFFFFu, cv.x, 1);
        cv.y += __shfl_xor_sync(0xFFFFFFFFu, cv.y, 1);

        // split stores across the pair
        float2* od = oD + (long long)l * 5;
        if (half == 0) {
            od[0] = r0; od[1] = r1; od[2] = r2;
        } else {
            od[3] = r3; od[4] = r4;
            oC[l] = cv;
        }

        // next carry prob: softmax(c)[0] = sigmoid(c0 - c1)
        p0 = 1.0f / (1.0f + expf(cv.y - cv.x));
    }
}

extern "C" void kernel_launch(void* const* d_in, const int* in_sizes, int n_in,
                              void* d_out, int out_size)
{
    const int*   A  = (const int*)  d_in[0];
    const int*   Bd = (const int*)  d_in[1];
    const float* Ea = (const float*)d_in[2];
    const float* Eb = (const float*)d_in[3];
    const float* W1 = (const float*)d_in[4];
    const float* b1 = (const float*)d_in[5];
    const float* W2 = (const float*)d_in[6];
    const float* b2 = (const float*)d_in[7];
    const float* Wd = (const float*)d_in[8];
    const float* bd = (const float*)d_in[9];
    const float* Wc = (const float*)d_in[10];
    const float* bc = (const float*)d_in[11];

    int Bn = in_sizes[0] / 64;
    int grid = (Bn + 63) / 64;      // 64 rows per block (128 threads, 2 per row)
    mlp_seq_kernel<<<grid, 128>>>(A, Bd, Ea, Eb, W1, b1, W2, b2, Wd, bd, Wc, bc,
                                  (float*)d_out, Bn);
}